// round 6
// baseline (speedup 1.0000x reference)
#include <cuda_runtime.h>
#include <cuda_bf16.h>
#include <math_constants.h>
#include <cstdint>

// Problem constants
#define B   4
#define S   2048
#define NX  1024
#define H   16
#define D   64
#define M_TOT (B * S)   // 8192

// Scratch
__device__ float g_qkv[(size_t)M_TOT * 3 * NX];   // (8192, 3072)
__device__ float g_ctx[(size_t)M_TOT * NX];       // (8192, 1024)
__device__ float g_wt1[(size_t)3 * NX * NX];      // c_attn_w^T, tf32
__device__ float g_wt2[(size_t)NX * NX];          // c_proj_w^T, tf32
__device__ float g_kc[(size_t)64 * S * D];        // K tf32, [bh][s][d-pperm]
__device__ float g_vt[(size_t)64 * D * S];        // V tf32, [bh][d][s-pperm]

// ---------------------------------------------------------------------------
// Helpers
// ---------------------------------------------------------------------------
__device__ __forceinline__ uint32_t f2tf32(float x) {
    uint32_t u;
    asm("cvt.rna.tf32.f32 %0, %1;" : "=r"(u) : "f"(x));
    return u;
}
__device__ __forceinline__ float f2tf32f(float x) {
    return __uint_as_float(f2tf32(x));
}

// mma.sync m16n8k8 tf32: D = A*B + D (fp32 accum)
__device__ __forceinline__ void mma8(float* c, const uint32_t* a, const uint32_t* b) {
    asm volatile(
        "mma.sync.aligned.m16n8k8.row.col.f32.tf32.tf32.f32 "
        "{%0,%1,%2,%3}, {%4,%5,%6,%7}, {%8,%9}, {%0,%1,%2,%3};"
        : "+f"(c[0]), "+f"(c[1]), "+f"(c[2]), "+f"(c[3])
        : "r"(a[0]), "r"(a[1]), "r"(a[2]), "r"(a[3]), "r"(b[0]), "r"(b[1]));
}

// pair-permutation within 8-block: e -> 2*(e&3) + ((e>>2)&1); pinv inverts it
__device__ __forceinline__ int pinv(int p) {
    return (p & ~7) | (((p & 7) >> 1) + 4 * (p & 1));
}

// ---------------------------------------------------------------------------
// Weight transpose + tf32 convert: Wt[n][k] = tf32(W[k][n])
// ---------------------------------------------------------------------------
__global__ void transpose_cvt(const float* __restrict__ W, float* __restrict__ Wt,
                              int K, int N)
{
    __shared__ float t[32][33];
    const int k0 = blockIdx.y * 32, n0 = blockIdx.x * 32;
    const int x = threadIdx.x, y = threadIdx.y;   // 32 x 8
#pragma unroll
    for (int i = 0; i < 32; i += 8)
        t[y + i][x] = W[(size_t)(k0 + y + i) * N + n0 + x];
    __syncthreads();
#pragma unroll
    for (int i = 0; i < 32; i += 8)
        Wt[(size_t)(n0 + y + i) * K + k0 + x] = f2tf32f(t[x][y + i]);
}

// ---------------------------------------------------------------------------
// Prep K/V for flash: tf32-convert, pair-permute, transpose V.
// grid (32 s-tiles, 64 bh), 256 threads.
// ---------------------------------------------------------------------------
__global__ __launch_bounds__(256)
void prep_kv(const float* __restrict__ qkv, float* __restrict__ kc,
             float* __restrict__ vt)
{
    __shared__ float vs[64][65];
    const int bh = blockIdx.y;
    const int b = bh >> 4, h = bh & 15;
    const int s0 = blockIdx.x * 64;
    const int tid = threadIdx.x;

    const float* kbase = qkv + (size_t)b * S * (3 * NX) + NX + h * D;
    const float* vbase = qkv + (size_t)b * S * (3 * NX) + 2 * NX + h * D;

    for (int idx = tid; idx < 64 * 16; idx += 256) {
        const int r  = idx >> 4;     // s row
        const int ve = idx & 15;
        const size_t grow = (size_t)(s0 + r) * (3 * NX) + ve * 4;
        // K -> kc[bh][s][pperm(d)]
        float4 kv = *(const float4*)(kbase + grow);
        float* out = kc + ((size_t)bh * S + s0 + r) * D + (ve >> 1) * 8 + (ve & 1);
        out[0] = f2tf32f(kv.x);
        out[2] = f2tf32f(kv.y);
        out[4] = f2tf32f(kv.z);
        out[6] = f2tf32f(kv.w);
        // V -> smem transpose tile vs[d][s]
        float4 vv = *(const float4*)(vbase + grow);
        vs[4 * ve + 0][r] = vv.x;
        vs[4 * ve + 1][r] = vv.y;
        vs[4 * ve + 2][r] = vv.z;
        vs[4 * ve + 3][r] = vv.w;
    }
    __syncthreads();

    for (int idx = tid; idx < 64 * 16; idx += 256) {
        const int d  = idx >> 4;
        const int ve = idx & 15;
        const int pb = ve * 4;
        float4 ov;
        ov.x = f2tf32f(vs[d][pinv(pb + 0)]);
        ov.y = f2tf32f(vs[d][pinv(pb + 1)]);
        ov.z = f2tf32f(vs[d][pinv(pb + 2)]);
        ov.w = f2tf32f(vs[d][pinv(pb + 3)]);
        *(float4*)(vt + ((size_t)bh * D + d) * S + s0 + pb) = ov;
    }
}

// ---------------------------------------------------------------------------
// tf32 mma GEMM (unchanged round-5): C[M,N] = A[M,K] @ Bt[N,K]^T + bias[N]
// ---------------------------------------------------------------------------
#define GLD 36

__global__ __launch_bounds__(256)
void gemm_mma(const float* __restrict__ A, const float* __restrict__ Bt,
              const float* __restrict__ bias, float* __restrict__ C,
              int M, int N, int K)
{
    __shared__ float As[128][GLD];
    __shared__ float Bs[128][GLD];

    const int tid  = threadIdx.x;
    const int wid  = tid >> 5;
    const int lane = tid & 31;
    const int g    = lane >> 2;
    const int tig  = lane & 3;

    const int brow = blockIdx.y * 128;
    const int bcol = blockIdx.x * 128;
    const int wm = (wid >> 2) * 64;
    const int wn = (wid & 3) * 32;

    float c[4][4][4];
#pragma unroll
    for (int mi = 0; mi < 4; mi++)
#pragma unroll
        for (int ni = 0; ni < 4; ni++)
#pragma unroll
            for (int j = 0; j < 4; j++) c[mi][ni][j] = 0.f;

    for (int k0 = 0; k0 < K; k0 += 32) {
        __syncthreads();
#pragma unroll
        for (int i = 0; i < 4; i++) {
            const int v = tid + i * 256;
            const int r  = v >> 3;
            const int ve = v & 7;
            float4 av = *(const float4*)(A + (size_t)(brow + r) * K + k0 + ve * 4);
            float4 ac;
            ac.x = f2tf32f(av.x); ac.y = f2tf32f(av.y);
            ac.z = f2tf32f(av.z); ac.w = f2tf32f(av.w);
            *(float4*)&As[r][ve * 4] = ac;
            float4 bv = *(const float4*)(Bt + (size_t)(bcol + r) * K + k0 + ve * 4);
            *(float4*)&Bs[r][ve * 4] = bv;
        }
        __syncthreads();

#pragma unroll
        for (int ks = 0; ks < 4; ks++) {
            const int kk = ks * 8;
            uint32_t af[4][4], bf[4][2];
#pragma unroll
            for (int mi = 0; mi < 4; mi++) {
                const int r = wm + mi * 16;
                af[mi][0] = __float_as_uint(As[r + g][kk + tig]);
                af[mi][1] = __float_as_uint(As[r + g + 8][kk + tig]);
                af[mi][2] = __float_as_uint(As[r + g][kk + tig + 4]);
                af[mi][3] = __float_as_uint(As[r + g + 8][kk + tig + 4]);
            }
#pragma unroll
            for (int ni = 0; ni < 4; ni++) {
                const int r = wn + ni * 8;
                bf[ni][0] = __float_as_uint(Bs[r + g][kk + tig]);
                bf[ni][1] = __float_as_uint(Bs[r + g][kk + tig + 4]);
            }
#pragma unroll
            for (int mi = 0; mi < 4; mi++)
#pragma unroll
                for (int ni = 0; ni < 4; ni++)
                    mma8(c[mi][ni], af[mi], bf[ni]);
        }
    }

#pragma unroll
    for (int mi = 0; mi < 4; mi++) {
        const int row0 = brow + wm + mi * 16 + g;
#pragma unroll
        for (int ni = 0; ni < 4; ni++) {
            const int col = bcol + wn + ni * 8 + 2 * tig;
            float2 bb = *(const float2*)(bias + col);
            float2 v0, v1;
            v0.x = c[mi][ni][0] + bb.x; v0.y = c[mi][ni][1] + bb.y;
            v1.x = c[mi][ni][2] + bb.x; v1.y = c[mi][ni][3] + bb.y;
            *(float2*)(C + (size_t)row0 * N + col) = v0;
            *(float2*)(C + (size_t)(row0 + 8) * N + col) = v1;
        }
    }
}

// ---------------------------------------------------------------------------
// Flash attention, staging-free: B-fragments via LDG.64 from g_kc / g_vt.
// Block: 4 warps, TQ=64, TK=64, 4 CTAs/SM. Smem: P buffer (aliases Q stage)
// + per-batch mask copy. No __syncthreads in the main loop.
// ---------------------------------------------------------------------------
#define PP 68

__global__ void __launch_bounds__(128, 4)
flash_attn_mma(const float* __restrict__ qkv, const float* __restrict__ kc,
               const float* __restrict__ vt, const float* __restrict__ mask,
               float* __restrict__ ctx)
{
    extern __shared__ float sm[];
    float* Ps  = sm;               // [64][PP]  Q staging, then P
    float* mks = Ps + 64 * PP;     // [2048]    mask for this batch

    const int bh = blockIdx.y;
    const int b  = bh >> 4;
    const int h  = bh & 15;
    const int q0 = blockIdx.x * 64;

    const int tid  = threadIdx.x;
    const int wid  = tid >> 5;
    const int lane = tid & 31;
    const int g    = lane >> 2;
    const int tig  = lane & 3;
    const int m0   = wid * 16;

    // Copy mask for this batch (2048 floats)
    for (int i = tid; i < 512; i += 128)
        *(float4*)&mks[i * 4] = *(const float4*)&mask[(size_t)b * S + i * 4];

    // Stage Q (tf32) into Ps, hoist fragments
    const float* qptr = qkv + (size_t)b * S * (3 * NX) + (size_t)h * D;
    for (int idx = tid; idx < 64 * 16; idx += 128) {
        const int r  = idx >> 4;
        const int ve = idx & 15;
        float4 qa = *(const float4*)(qptr + (size_t)(q0 + r) * (3 * NX) + ve * 4);
        float* dst = &Ps[r * PP + ve * 4];
        dst[0] = f2tf32f(qa.x);
        dst[1] = f2tf32f(qa.y);
        dst[2] = f2tf32f(qa.z);
        dst[3] = f2tf32f(qa.w);
    }
    __syncthreads();

    uint32_t aq[8][4];
#pragma unroll
    for (int ks = 0; ks < 8; ks++) {
        const int kk = ks * 8;
        aq[ks][0] = __float_as_uint(Ps[(m0 + g) * PP + kk + tig]);
        aq[ks][1] = __float_as_uint(Ps[(m0 + g + 8) * PP + kk + tig]);
        aq[ks][2] = __float_as_uint(Ps[(m0 + g) * PP + kk + tig + 4]);
        aq[ks][3] = __float_as_uint(Ps[(m0 + g + 8) * PP + kk + tig + 4]);
    }
    __syncthreads();   // everyone done reading Q before P overwrites

    float mi0 = -CUDART_INF_F, mi1 = -CUDART_INF_F;
    float li0 = 0.f, li1 = 0.f;
    float o[8][4];
#pragma unroll
    for (int ni = 0; ni < 8; ni++)
#pragma unroll
        for (int j = 0; j < 4; j++) o[ni][j] = 0.f;

    // Per-thread fragment base pointers (advance by tile each iteration)
    const float* krow = kc + ((size_t)bh * S + g) * D + 2 * tig;        // + ni*8*D + ks*8
    const float* vrow = vt + ((size_t)bh * D + g) * S + 2 * tig;        // + ni*8*S + ks*8

    for (int kt = 0; kt < S / 64; kt++) {
        const int k0g = kt * 64;

        // ---- QK^T : B-frags direct LDG.64 from kc
        float c[8][4];
#pragma unroll
        for (int ni = 0; ni < 8; ni++)
#pragma unroll
            for (int j = 0; j < 4; j++) c[ni][j] = 0.f;

#pragma unroll
        for (int ks = 0; ks < 8; ks++) {
            uint32_t bf[8][2];
#pragma unroll
            for (int ni = 0; ni < 8; ni++) {
                float2 bb = __ldg((const float2*)(krow + (size_t)ni * 8 * D + ks * 8));
                bf[ni][0] = __float_as_uint(bb.x);
                bf[ni][1] = __float_as_uint(bb.y);
            }
#pragma unroll
            for (int ni = 0; ni < 8; ni++)
                mma8(c[ni], aq[ks], bf[ni]);
        }

        // ---- scale + mask (from smem mask copy)
#pragma unroll
        for (int ni = 0; ni < 8; ni++) {
            float2 mm = *(const float2*)&mks[k0g + ni * 8 + 2 * tig];
            c[ni][0] = fmaf(c[ni][0], 0.125f, mm.x);
            c[ni][1] = fmaf(c[ni][1], 0.125f, mm.y);
            c[ni][2] = fmaf(c[ni][2], 0.125f, mm.x);
            c[ni][3] = fmaf(c[ni][3], 0.125f, mm.y);
        }

        // ---- online softmax
        float mt0 = -CUDART_INF_F, mt1 = -CUDART_INF_F;
#pragma unroll
        for (int ni = 0; ni < 8; ni++) {
            mt0 = fmaxf(mt0, fmaxf(c[ni][0], c[ni][1]));
            mt1 = fmaxf(mt1, fmaxf(c[ni][2], c[ni][3]));
        }
        mt0 = fmaxf(mt0, __shfl_xor_sync(0xffffffffu, mt0, 1));
        mt0 = fmaxf(mt0, __shfl_xor_sync(0xffffffffu, mt0, 2));
        mt1 = fmaxf(mt1, __shfl_xor_sync(0xffffffffu, mt1, 1));
        mt1 = fmaxf(mt1, __shfl_xor_sync(0xffffffffu, mt1, 2));

        const float mn0 = fmaxf(mi0, mt0);
        const float mn1 = fmaxf(mi1, mt1);
        const float fac0 = __expf(mi0 - mn0);
        const float fac1 = __expf(mi1 - mn1);
        mi0 = mn0; mi1 = mn1;

        float lt0 = 0.f, lt1 = 0.f;
#pragma unroll
        for (int ni = 0; ni < 8; ni++) {
            c[ni][0] = __expf(c[ni][0] - mn0);
            c[ni][1] = __expf(c[ni][1] - mn0);
            c[ni][2] = __expf(c[ni][2] - mn1);
            c[ni][3] = __expf(c[ni][3] - mn1);
            lt0 += c[ni][0] + c[ni][1];
            lt1 += c[ni][2] + c[ni][3];
        }
        lt0 += __shfl_xor_sync(0xffffffffu, lt0, 1);
        lt0 += __shfl_xor_sync(0xffffffffu, lt0, 2);
        lt1 += __shfl_xor_sync(0xffffffffu, lt1, 1);
        lt1 += __shfl_xor_sync(0xffffffffu, lt1, 2);
        li0 = li0 * fac0 + lt0;
        li1 = li1 * fac1 + lt1;

#pragma unroll
        for (int ni = 0; ni < 8; ni++) {
            o[ni][0] *= fac0; o[ni][1] *= fac0;
            o[ni][2] *= fac1; o[ni][3] *= fac1;
        }

        // ---- store P (tf32) to own rows (warp-private)
#pragma unroll
        for (int ni = 0; ni < 8; ni++) {
            const int jc = ni * 8 + 2 * tig;
            float2 p0, p1;
            p0.x = f2tf32f(c[ni][0]);
            p0.y = f2tf32f(c[ni][1]);
            p1.x = f2tf32f(c[ni][2]);
            p1.y = f2tf32f(c[ni][3]);
            *(float2*)&Ps[(m0 + g) * PP + jc]     = p0;
            *(float2*)&Ps[(m0 + g + 8) * PP + jc] = p1;
        }
        __syncwarp();

        // ---- O += P @ V : B-frags direct LDG.64 from vt
#pragma unroll
        for (int ks = 0; ks < 8; ks++) {
            const int kk = ks * 8;
            uint32_t ap[4];
            ap[0] = __float_as_uint(Ps[(m0 + g) * PP + kk + tig]);
            ap[1] = __float_as_uint(Ps[(m0 + g + 8) * PP + kk + tig]);
            ap[2] = __float_as_uint(Ps[(m0 + g) * PP + kk + tig + 4]);
            ap[3] = __float_as_uint(Ps[(m0 + g + 8) * PP + kk + tig + 4]);
            uint32_t bf[8][2];
#pragma unroll
            for (int ni = 0; ni < 8; ni++) {
                float2 bb = __ldg((const float2*)(vrow + (size_t)ni * 8 * S + ks * 8));
                bf[ni][0] = __float_as_uint(bb.x);
                bf[ni][1] = __float_as_uint(bb.y);
            }
#pragma unroll
            for (int ni = 0; ni < 8; ni++)
                mma8(o[ni], ap, bf[ni]);
        }
        __syncwarp();   // all P reads done before next tile overwrites

        krow += 64 * D;   // next 64 keys
        vrow += 64;       // next 64 key-columns
    }

    // ---- normalize + write merged-heads context
    const float inv0 = 1.f / li0;
    const float inv1 = 1.f / li1;
    const size_t row0 = (size_t)b * S + q0 + m0 + g;
#pragma unroll
    for (int ni = 0; ni < 8; ni++) {
        const int col = h * D + ni * 8 + 2 * tig;
        float2 v0, v1;
        v0.x = o[ni][0] * inv0; v0.y = o[ni][1] * inv0;
        v1.x = o[ni][2] * inv1; v1.y = o[ni][3] * inv1;
        *(float2*)(ctx + row0 * NX + col)       = v0;
        *(float2*)(ctx + (row0 + 8) * NX + col) = v1;
    }
}

// ---------------------------------------------------------------------------
// Launch
// ---------------------------------------------------------------------------
extern "C" void kernel_launch(void* const* d_in, const int* in_sizes, int n_in,
                              void* d_out, int out_size)
{
    const float* x        = (const float*)d_in[0];
    const float* mask     = (const float*)d_in[1];
    const float* c_attn_w = (const float*)d_in[2];
    const float* c_attn_b = (const float*)d_in[3];
    const float* c_proj_w = (const float*)d_in[4];
    const float* c_proj_b = (const float*)d_in[5];
    float* out = (float*)d_out;

    float *qkv, *ctx, *wt1, *wt2, *kc, *vt;
    cudaGetSymbolAddress((void**)&qkv, g_qkv);
    cudaGetSymbolAddress((void**)&ctx, g_ctx);
    cudaGetSymbolAddress((void**)&wt1, g_wt1);
    cudaGetSymbolAddress((void**)&wt2, g_wt2);
    cudaGetSymbolAddress((void**)&kc,  g_kc);
    cudaGetSymbolAddress((void**)&vt,  g_vt);

    // 0) Transpose + tf32-convert weights
    transpose_cvt<<<dim3(3 * NX / 32, NX / 32), dim3(32, 8)>>>(c_attn_w, wt1, NX, 3 * NX);
    transpose_cvt<<<dim3(NX / 32, NX / 32),     dim3(32, 8)>>>(c_proj_w, wt2, NX, NX);

    // 1) QKV projection
    gemm_mma<<<dim3(3 * NX / 128, M_TOT / 128), 256>>>(x, wt1, c_attn_b, qkv,
                                                       M_TOT, 3 * NX, NX);

    // 1.5) Prep K/V (tf32 + permute + V transpose)
    prep_kv<<<dim3(S / 64, 64), 256>>>(qkv, kc, vt);

    // 2) Flash attention (staging-free)
    {
        const int smem = (64 * PP + S) * (int)sizeof(float);  // 25600 B
        cudaFuncSetAttribute(flash_attn_mma, cudaFuncAttributeMaxDynamicSharedMemorySize, smem);
        dim3 grid(S / 64, B * H);
        flash_attn_mma<<<grid, 128, smem>>>(qkv, kc, vt, mask, ctx);
    }

    // 3) Output projection
    gemm_mma<<<dim3(NX / 128, M_TOT / 128), 256>>>(ctx, wt2, c_proj_b, out,
                                                   M_TOT, NX, NX);
}

// round 7
// speedup vs baseline: 1.5458x; 1.5458x over previous
#include <cuda_runtime.h>
#include <cuda_bf16.h>
#include <math_constants.h>
#include <cstdint>

// Problem constants
#define B   4
#define S   2048
#define NX  1024
#define H   16
#define D   64
#define M_TOT (B * S)   // 8192

// Scratch
__device__ float g_qkv[(size_t)M_TOT * 3 * NX];   // (8192, 3072)
__device__ float g_ctx[(size_t)M_TOT * NX];       // (8192, 1024)
__device__ float g_wt1[(size_t)3 * NX * NX];      // c_attn_w^T, tf32
__device__ float g_wt2[(size_t)NX * NX];          // c_proj_w^T, tf32
__device__ float g_kc[(size_t)64 * S * D];        // K tf32, [bh][s][d-pperm]
__device__ float g_vt[(size_t)64 * D * S];        // V tf32, [bh][d][s-pperm]

// ---------------------------------------------------------------------------
// Helpers
// ---------------------------------------------------------------------------
__device__ __forceinline__ uint32_t f2tf32(float x) {
    uint32_t u;
    asm("cvt.rna.tf32.f32 %0, %1;" : "=r"(u) : "f"(x));
    return u;
}
__device__ __forceinline__ float f2tf32f(float x) {
    return __uint_as_float(f2tf32(x));
}

// mma.sync m16n8k8 tf32: D = A*B + D (fp32 accum)
__device__ __forceinline__ void mma8(float* c, const uint32_t* a, const uint32_t* b) {
    asm volatile(
        "mma.sync.aligned.m16n8k8.row.col.f32.tf32.tf32.f32 "
        "{%0,%1,%2,%3}, {%4,%5,%6,%7}, {%8,%9}, {%0,%1,%2,%3};"
        : "+f"(c[0]), "+f"(c[1]), "+f"(c[2]), "+f"(c[3])
        : "r"(a[0]), "r"(a[1]), "r"(a[2]), "r"(a[3]), "r"(b[0]), "r"(b[1]));
}

// inverse of pair-permutation e -> 2*(e&3) + ((e>>2)&1)
__device__ __forceinline__ int pinv(int p) {
    return (p & ~7) | (((p & 7) >> 1) + 4 * (p & 1));
}

// ---------------------------------------------------------------------------
// Weight transpose + tf32 convert: Wt[n][k] = tf32(W[k][n])
// ---------------------------------------------------------------------------
__global__ void transpose_cvt(const float* __restrict__ W, float* __restrict__ Wt,
                              int K, int N)
{
    __shared__ float t[32][33];
    const int k0 = blockIdx.y * 32, n0 = blockIdx.x * 32;
    const int x = threadIdx.x, y = threadIdx.y;   // 32 x 8
#pragma unroll
    for (int i = 0; i < 32; i += 8)
        t[y + i][x] = W[(size_t)(k0 + y + i) * N + n0 + x];
    __syncthreads();
#pragma unroll
    for (int i = 0; i < 32; i += 8)
        Wt[(size_t)(n0 + y + i) * K + k0 + x] = f2tf32f(t[x][y + i]);
}

// ---------------------------------------------------------------------------
// Prep K/V for flash: tf32-convert, pair-permute, transpose V.
// grid (32 s-tiles, 64 bh), 256 threads.
// ---------------------------------------------------------------------------
__global__ __launch_bounds__(256)
void prep_kv(const float* __restrict__ qkv, float* __restrict__ kc,
             float* __restrict__ vt)
{
    __shared__ float vs[64][65];
    const int bh = blockIdx.y;
    const int b = bh >> 4, h = bh & 15;
    const int s0 = blockIdx.x * 64;
    const int tid = threadIdx.x;

    const float* kbase = qkv + (size_t)b * S * (3 * NX) + NX + h * D;
    const float* vbase = qkv + (size_t)b * S * (3 * NX) + 2 * NX + h * D;

    for (int idx = tid; idx < 64 * 16; idx += 256) {
        const int r  = idx >> 4;     // s row
        const int ve = idx & 15;
        const size_t grow = (size_t)(s0 + r) * (3 * NX) + ve * 4;
        // K -> kc[bh][s][pperm(d)]
        float4 kv = *(const float4*)(kbase + grow);
        float* out = kc + ((size_t)bh * S + s0 + r) * D + (ve >> 1) * 8 + (ve & 1);
        out[0] = f2tf32f(kv.x);
        out[2] = f2tf32f(kv.y);
        out[4] = f2tf32f(kv.z);
        out[6] = f2tf32f(kv.w);
        // V -> smem transpose tile vs[d][s]
        float4 vv = *(const float4*)(vbase + grow);
        vs[4 * ve + 0][r] = vv.x;
        vs[4 * ve + 1][r] = vv.y;
        vs[4 * ve + 2][r] = vv.z;
        vs[4 * ve + 3][r] = vv.w;
    }
    __syncthreads();

    for (int idx = tid; idx < 64 * 16; idx += 256) {
        const int d  = idx >> 4;
        const int ve = idx & 15;
        const int pb = ve * 4;
        float4 ov;
        ov.x = f2tf32f(vs[d][pinv(pb + 0)]);
        ov.y = f2tf32f(vs[d][pinv(pb + 1)]);
        ov.z = f2tf32f(vs[d][pinv(pb + 2)]);
        ov.w = f2tf32f(vs[d][pinv(pb + 3)]);
        *(float4*)(vt + ((size_t)bh * D + d) * S + s0 + pb) = ov;
    }
}

// ---------------------------------------------------------------------------
// tf32 mma GEMM: C[M,N] = A[M,K] @ Bt[N,K]^T + bias[N]
// Block 128x128, K-tile 32, 256 threads = 8 warps; warp tile 64x32.
// ---------------------------------------------------------------------------
#define GLD 36

__global__ __launch_bounds__(256)
void gemm_mma(const float* __restrict__ A, const float* __restrict__ Bt,
              const float* __restrict__ bias, float* __restrict__ C,
              int M, int N, int K)
{
    __shared__ float As[128][GLD];
    __shared__ float Bs[128][GLD];

    const int tid  = threadIdx.x;
    const int wid  = tid >> 5;
    const int lane = tid & 31;
    const int g    = lane >> 2;
    const int tig  = lane & 3;

    const int brow = blockIdx.y * 128;
    const int bcol = blockIdx.x * 128;
    const int wm = (wid >> 2) * 64;
    const int wn = (wid & 3) * 32;

    float c[4][4][4];
#pragma unroll
    for (int mi = 0; mi < 4; mi++)
#pragma unroll
        for (int ni = 0; ni < 4; ni++)
#pragma unroll
            for (int j = 0; j < 4; j++) c[mi][ni][j] = 0.f;

    for (int k0 = 0; k0 < K; k0 += 32) {
        __syncthreads();
#pragma unroll
        for (int i = 0; i < 4; i++) {
            const int v = tid + i * 256;
            const int r  = v >> 3;
            const int ve = v & 7;
            float4 av = *(const float4*)(A + (size_t)(brow + r) * K + k0 + ve * 4);
            float4 ac;
            ac.x = f2tf32f(av.x); ac.y = f2tf32f(av.y);
            ac.z = f2tf32f(av.z); ac.w = f2tf32f(av.w);
            *(float4*)&As[r][ve * 4] = ac;
            float4 bv = *(const float4*)(Bt + (size_t)(bcol + r) * K + k0 + ve * 4);
            *(float4*)&Bs[r][ve * 4] = bv;
        }
        __syncthreads();

#pragma unroll
        for (int ks = 0; ks < 4; ks++) {
            const int kk = ks * 8;
            uint32_t af[4][4], bf[4][2];
#pragma unroll
            for (int mi = 0; mi < 4; mi++) {
                const int r = wm + mi * 16;
                af[mi][0] = __float_as_uint(As[r + g][kk + tig]);
                af[mi][1] = __float_as_uint(As[r + g + 8][kk + tig]);
                af[mi][2] = __float_as_uint(As[r + g][kk + tig + 4]);
                af[mi][3] = __float_as_uint(As[r + g + 8][kk + tig + 4]);
            }
#pragma unroll
            for (int ni = 0; ni < 4; ni++) {
                const int r = wn + ni * 8;
                bf[ni][0] = __float_as_uint(Bs[r + g][kk + tig]);
                bf[ni][1] = __float_as_uint(Bs[r + g][kk + tig + 4]);
            }
#pragma unroll
            for (int mi = 0; mi < 4; mi++)
#pragma unroll
                for (int ni = 0; ni < 4; ni++)
                    mma8(c[mi][ni], af[mi], bf[ni]);
        }
    }

#pragma unroll
    for (int mi = 0; mi < 4; mi++) {
        const int row0 = brow + wm + mi * 16 + g;
#pragma unroll
        for (int ni = 0; ni < 4; ni++) {
            const int col = bcol + wn + ni * 8 + 2 * tig;
            float2 bb = *(const float2*)(bias + col);
            float2 v0, v1;
            v0.x = c[mi][ni][0] + bb.x; v0.y = c[mi][ni][1] + bb.y;
            v1.x = c[mi][ni][2] + bb.x; v1.y = c[mi][ni][3] + bb.y;
            *(float2*)(C + (size_t)row0 * N + col) = v0;
            *(float2*)(C + (size_t)(row0 + 8) * N + col) = v1;
        }
    }
}

// ---------------------------------------------------------------------------
// Flash attention with tf32 mma.
// Block: 4 warps, TQ=64, TK=64, 4 CTAs/SM.
// K/V staged into smem as PURE float4 copies from pre-permuted, pre-converted
// g_kc/g_vt (no cvt, no transpose, no conflicts in the loop).
// Stores at stride KP=72: phase banks (72r+4ve) mod 32 all distinct.
// Fragment reads at stride 72: conflict-free (banks 8g+2tig per phase).
// Ps (stride 68) aliases Q staging.
// ---------------------------------------------------------------------------
#define KP 72
#define PP 68

__global__ void __launch_bounds__(128, 4)
flash_attn_mma(const float* __restrict__ qkv, const float* __restrict__ kc,
               const float* __restrict__ vt, const float* __restrict__ mask,
               float* __restrict__ ctx)
{
    extern __shared__ float sm[];
    float* Ps = sm;                    // [64][PP]  Q staging, then P
    float* Ks = Ps + 64 * PP;          // [64][KP]  (key, d-permuted)
    float* Vt = Ks + 64 * KP;          // [64][KP]  (d, key-permuted)
    float* mk = Vt + 64 * KP;          // [64]

    const int bh = blockIdx.y;
    const int b  = bh >> 4;
    const int h  = bh & 15;
    const int q0 = blockIdx.x * 64;

    const int tid  = threadIdx.x;
    const int wid  = tid >> 5;
    const int lane = tid & 31;
    const int g    = lane >> 2;
    const int tig  = lane & 3;
    const int m0   = wid * 16;

    // Stage Q (tf32) into the Ps region, hoist fragments, then Ps is free.
    const float* qptr = qkv + (size_t)b * S * (3 * NX) + (size_t)h * D;
    for (int idx = tid; idx < 64 * 16; idx += 128) {
        const int r  = idx >> 4;
        const int ve = idx & 15;
        float4 qa = *(const float4*)(qptr + (size_t)(q0 + r) * (3 * NX) + ve * 4);
        float* dst = &Ps[r * PP + ve * 4];
        dst[0] = f2tf32f(qa.x);
        dst[1] = f2tf32f(qa.y);
        dst[2] = f2tf32f(qa.z);
        dst[3] = f2tf32f(qa.w);
    }
    __syncthreads();

    uint32_t aq[8][4];
#pragma unroll
    for (int ks = 0; ks < 8; ks++) {
        const int kk = ks * 8;
        aq[ks][0] = __float_as_uint(Ps[(m0 + g) * PP + kk + tig]);
        aq[ks][1] = __float_as_uint(Ps[(m0 + g + 8) * PP + kk + tig]);
        aq[ks][2] = __float_as_uint(Ps[(m0 + g) * PP + kk + tig + 4]);
        aq[ks][3] = __float_as_uint(Ps[(m0 + g + 8) * PP + kk + tig + 4]);
    }

    float mi0 = -CUDART_INF_F, mi1 = -CUDART_INF_F;
    float li0 = 0.f, li1 = 0.f;
    float o[8][4];
#pragma unroll
    for (int ni = 0; ni < 8; ni++)
#pragma unroll
        for (int j = 0; j < 4; j++) o[ni][j] = 0.f;

    const float* kcb = kc + (size_t)bh * S * D;   // [s][d-pperm]
    const float* vtb = vt + (size_t)bh * D * S;   // [d][s-pperm]

    for (int kt = 0; kt < S / 64; kt++) {
        const int k0g = kt * 64;
        __syncthreads();   // previous iteration's Ks/Vt/Ps reads complete

        // Stage K/V tiles: pure float4 copies, coalesced, conflict-free stores
        for (int idx = tid; idx < 64 * 16; idx += 128) {
            const int r  = idx >> 4;       // K: key row   V: d row
            const int ve = idx & 15;
            float4 kv = *(const float4*)(kcb + (size_t)(k0g + r) * D + ve * 4);
            *(float4*)&Ks[r * KP + ve * 4] = kv;
            float4 vv = *(const float4*)(vtb + (size_t)r * S + k0g + ve * 4);
            *(float4*)&Vt[r * KP + ve * 4] = vv;
        }
        if (tid < 16)
            *(float4*)&mk[tid * 4] = *(const float4*)&mask[(size_t)b * S + k0g + tid * 4];
        __syncthreads();

        // ---- QK^T
        float c[8][4];
#pragma unroll
        for (int ni = 0; ni < 8; ni++)
#pragma unroll
            for (int j = 0; j < 4; j++) c[ni][j] = 0.f;

#pragma unroll
        for (int ks = 0; ks < 8; ks++) {
            const int kk = ks * 8 + 2 * tig;
            uint32_t bf[8][2];
#pragma unroll
            for (int ni = 0; ni < 8; ni++) {
                float2 bb = *(const float2*)&Ks[(ni * 8 + g) * KP + kk];
                bf[ni][0] = __float_as_uint(bb.x);
                bf[ni][1] = __float_as_uint(bb.y);
            }
#pragma unroll
            for (int ni = 0; ni < 8; ni++)
                mma8(c[ni], aq[ks], bf[ni]);
        }

        // ---- scale + mask
#pragma unroll
        for (int ni = 0; ni < 8; ni++) {
            float2 mm = *(const float2*)&mk[ni * 8 + 2 * tig];
            c[ni][0] = fmaf(c[ni][0], 0.125f, mm.x);
            c[ni][1] = fmaf(c[ni][1], 0.125f, mm.y);
            c[ni][2] = fmaf(c[ni][2], 0.125f, mm.x);
            c[ni][3] = fmaf(c[ni][3], 0.125f, mm.y);
        }

        // ---- online softmax (rows g / g+8, reduce over tig lanes)
        float mt0 = -CUDART_INF_F, mt1 = -CUDART_INF_F;
#pragma unroll
        for (int ni = 0; ni < 8; ni++) {
            mt0 = fmaxf(mt0, fmaxf(c[ni][0], c[ni][1]));
            mt1 = fmaxf(mt1, fmaxf(c[ni][2], c[ni][3]));
        }
        mt0 = fmaxf(mt0, __shfl_xor_sync(0xffffffffu, mt0, 1));
        mt0 = fmaxf(mt0, __shfl_xor_sync(0xffffffffu, mt0, 2));
        mt1 = fmaxf(mt1, __shfl_xor_sync(0xffffffffu, mt1, 1));
        mt1 = fmaxf(mt1, __shfl_xor_sync(0xffffffffu, mt1, 2));

        const float mn0 = fmaxf(mi0, mt0);
        const float mn1 = fmaxf(mi1, mt1);
        const float fac0 = __expf(mi0 - mn0);
        const float fac1 = __expf(mi1 - mn1);
        mi0 = mn0; mi1 = mn1;

        float lt0 = 0.f, lt1 = 0.f;
#pragma unroll
        for (int ni = 0; ni < 8; ni++) {
            c[ni][0] = __expf(c[ni][0] - mn0);
            c[ni][1] = __expf(c[ni][1] - mn0);
            c[ni][2] = __expf(c[ni][2] - mn1);
            c[ni][3] = __expf(c[ni][3] - mn1);
            lt0 += c[ni][0] + c[ni][1];
            lt1 += c[ni][2] + c[ni][3];
        }
        lt0 += __shfl_xor_sync(0xffffffffu, lt0, 1);
        lt0 += __shfl_xor_sync(0xffffffffu, lt0, 2);
        lt1 += __shfl_xor_sync(0xffffffffu, lt1, 1);
        lt1 += __shfl_xor_sync(0xffffffffu, lt1, 2);
        li0 = li0 * fac0 + lt0;
        li1 = li1 * fac1 + lt1;

#pragma unroll
        for (int ni = 0; ni < 8; ni++) {
            o[ni][0] *= fac0; o[ni][1] *= fac0;
            o[ni][2] *= fac1; o[ni][3] *= fac1;
        }

        // ---- store P (tf32) to own rows (banks 4g+8ni+2tig: conflict-free)
#pragma unroll
        for (int ni = 0; ni < 8; ni++) {
            const int jc = ni * 8 + 2 * tig;
            float2 p0, p1;
            p0.x = f2tf32f(c[ni][0]);
            p0.y = f2tf32f(c[ni][1]);
            p1.x = f2tf32f(c[ni][2]);
            p1.y = f2tf32f(c[ni][3]);
            *(float2*)&Ps[(m0 + g) * PP + jc]     = p0;
            *(float2*)&Ps[(m0 + g + 8) * PP + jc] = p1;
        }
        __syncwarp();

        // ---- O += P @ V
#pragma unroll
        for (int ks = 0; ks < 8; ks++) {
            const int kk = ks * 8;
            uint32_t ap[4];
            ap[0] = __float_as_uint(Ps[(m0 + g) * PP + kk + tig]);
            ap[1] = __float_as_uint(Ps[(m0 + g + 8) * PP + kk + tig]);
            ap[2] = __float_as_uint(Ps[(m0 + g) * PP + kk + tig + 4]);
            ap[3] = __float_as_uint(Ps[(m0 + g + 8) * PP + kk + tig + 4]);
            const int kkp = kk + 2 * tig;
            uint32_t bf[8][2];
#pragma unroll
            for (int ni = 0; ni < 8; ni++) {
                float2 bb = *(const float2*)&Vt[(ni * 8 + g) * KP + kkp];
                bf[ni][0] = __float_as_uint(bb.x);
                bf[ni][1] = __float_as_uint(bb.y);
            }
#pragma unroll
            for (int ni = 0; ni < 8; ni++)
                mma8(o[ni], ap, bf[ni]);
        }
    }

    // ---- normalize + write merged-heads context
    const float inv0 = 1.f / li0;
    const float inv1 = 1.f / li1;
    const size_t row0 = (size_t)b * S + q0 + m0 + g;
#pragma unroll
    for (int ni = 0; ni < 8; ni++) {
        const int col = h * D + ni * 8 + 2 * tig;
        float2 v0, v1;
        v0.x = o[ni][0] * inv0; v0.y = o[ni][1] * inv0;
        v1.x = o[ni][2] * inv1; v1.y = o[ni][3] * inv1;
        *(float2*)(ctx + row0 * NX + col)       = v0;
        *(float2*)(ctx + (row0 + 8) * NX + col) = v1;
    }
}

// ---------------------------------------------------------------------------
// Launch
// ---------------------------------------------------------------------------
extern "C" void kernel_launch(void* const* d_in, const int* in_sizes, int n_in,
                              void* d_out, int out_size)
{
    const float* x        = (const float*)d_in[0];
    const float* mask     = (const float*)d_in[1];
    const float* c_attn_w = (const float*)d_in[2];
    const float* c_attn_b = (const float*)d_in[3];
    const float* c_proj_w = (const float*)d_in[4];
    const float* c_proj_b = (const float*)d_in[5];
    float* out = (float*)d_out;

    float *qkv, *ctx, *wt1, *wt2, *kc, *vt;
    cudaGetSymbolAddress((void**)&qkv, g_qkv);
    cudaGetSymbolAddress((void**)&ctx, g_ctx);
    cudaGetSymbolAddress((void**)&wt1, g_wt1);
    cudaGetSymbolAddress((void**)&wt2, g_wt2);
    cudaGetSymbolAddress((void**)&kc,  g_kc);
    cudaGetSymbolAddress((void**)&vt,  g_vt);

    // 0) Transpose + tf32-convert weights
    transpose_cvt<<<dim3(3 * NX / 32, NX / 32), dim3(32, 8)>>>(c_attn_w, wt1, NX, 3 * NX);
    transpose_cvt<<<dim3(NX / 32, NX / 32),     dim3(32, 8)>>>(c_proj_w, wt2, NX, NX);

    // 1) QKV projection
    gemm_mma<<<dim3(3 * NX / 128, M_TOT / 128), 256>>>(x, wt1, c_attn_b, qkv,
                                                       M_TOT, 3 * NX, NX);

    // 1.5) Prep K/V (tf32 + permute + V transpose)
    prep_kv<<<dim3(S / 64, 64), 256>>>(qkv, kc, vt);

    // 2) Flash attention (copy-only staging)
    {
        const int smem = (64 * PP + 2 * 64 * KP + 64) * (int)sizeof(float); // 54528 B
        cudaFuncSetAttribute(flash_attn_mma, cudaFuncAttributeMaxDynamicSharedMemorySize, smem);
        dim3 grid(S / 64, B * H);
        flash_attn_mma<<<grid, 128, smem>>>(qkv, kc, vt, mask, ctx);
    }

    // 3) Output projection
    gemm_mma<<<dim3(NX / 128, M_TOT / 128), 256>>>(ctx, wt2, c_proj_b, out,
                                                   M_TOT, NX, NX);
}